// round 3
// baseline (speedup 1.0000x reference)
#include <cuda_runtime.h>
#include <cuda_bf16.h>
#include <cstdint>

// Problem constants (fixed by the reference)
#define N_NODES 100000
#define D_FEAT  128
#define E_EDGES 1600000

// Static device scratch (allocation-free rule: __device__ globals)
__device__ float g_h   [(size_t)N_NODES * D_FEAT];  // dis-scaled linear output (gather source)
__device__ float g_agg [(size_t)N_NODES * D_FEAT];  // aggregation buffer (scatter target)
__device__ float g_deg [N_NODES];
__device__ float g_dis [N_NODES];
__device__ int2  g_edges[E_EDGES];                  // packed (row, col) int32

// ---------------------------------------------------------------------------
// Degree / normalization / edge packing
// ---------------------------------------------------------------------------
__global__ void deg_init_kernel(float* __restrict__ deg, int n) {
    int i = blockIdx.x * blockDim.x + threadIdx.x;
    if (i < n) deg[i] = 1.0f;   // self-loop contributes 1 to every node's degree
}

// Pack edge_index (int32, shape [2, E] row-major) -> int2, accumulate
// source-side degree in the same pass. Defensive bounds check: a bad index
// becomes a dropped edge (visible as rel_err), never an IMA.
__global__ void edge_pack_kernel(const int* __restrict__ ei,
                                 int2* __restrict__ edges,
                                 float* __restrict__ deg, int e) {
    int i = blockIdx.x * blockDim.x + threadIdx.x;
    if (i >= e) return;
    int r = ei[i];
    int c = ei[E_EDGES + i];
    if ((unsigned)r >= (unsigned)N_NODES || (unsigned)c >= (unsigned)N_NODES) {
        edges[i] = make_int2(0, 0);   // benign; also keeps scatter in-bounds
        return;
    }
    edges[i] = make_int2(r, c);
    atomicAdd(&deg[r], 1.0f);
}

__global__ void deg_fin_kernel(const float* __restrict__ deg, float* __restrict__ dis, int n) {
    int i = blockIdx.x * blockDim.x + threadIdx.x;
    if (i < n) dis[i] = rsqrtf(deg[i]);
}

// ---------------------------------------------------------------------------
// Fused GEMM: out_h[i] = out_agg[i] = dis[i] * (act(in[i]) @ W^T + b)
//   PRE==false: act(v) = v                     (layer 1, raw x input)
//   PRE==true : act(v) = relu(dis[i] * v)      (layers 2/3, fused prior-layer epilogue)
// BM=64, BN=128(full), BK=32, 256 threads, 8x4 register microtile.
// ---------------------------------------------------------------------------
template <bool PRE>
__global__ __launch_bounds__(256) void gemm_kernel(
    const float* __restrict__ in, const float* __restrict__ W,
    const float* __restrict__ b,  const float* __restrict__ dis,
    float* __restrict__ out_h, float* __restrict__ out_agg, int n)
{
    __shared__ float As[64 * 32];        // [row][k]
    __shared__ float Ws[32 * 128];       // transposed: [k][o]

    const int tx = threadIdx.x;
    const int block_row = blockIdx.x * 64;
    const int col_tile = tx & 31;        // cols col_tile*4 .. +3
    const int row_tile = tx >> 5;        // rows row_tile*8 .. +7

    float acc[8][4];
#pragma unroll
    for (int r = 0; r < 8; r++)
#pragma unroll
        for (int j = 0; j < 4; j++) acc[r][j] = 0.0f;

    for (int k0 = 0; k0 < D_FEAT; k0 += 32) {
        // --- A tile: 64x32 floats = 512 float4, 2 per thread ---
#pragma unroll
        for (int it = 0; it < 2; it++) {
            int idx = it * 256 + tx;                 // 0..511
            int r   = idx >> 3;                      // 8 float4 per row
            int c4  = (idx & 7) * 4;
            int grow = block_row + r;
            float4 v = make_float4(0.f, 0.f, 0.f, 0.f);
            if (grow < n) {
                v = *(const float4*)(in + (size_t)grow * D_FEAT + k0 + c4);
                if (PRE) {
                    float s = dis[grow];
                    v.x = fmaxf(v.x * s, 0.f);
                    v.y = fmaxf(v.y * s, 0.f);
                    v.z = fmaxf(v.z * s, 0.f);
                    v.w = fmaxf(v.w * s, 0.f);
                }
            }
            *(float4*)(As + r * 32 + c4) = v;
        }
        // --- W tile (transposed into Ws[k][o]): 4096 floats, 4 float4 loads/thread ---
#pragma unroll
        for (int it = 0; it < 4; it++) {
            int idx = it * 256 + tx;                 // 0..1023
            int o   = idx >> 3;                      // 8 float4 along k per o-row
            int kq  = (idx & 7) * 4;
            float4 v = *(const float4*)(W + (size_t)o * D_FEAT + k0 + kq);
            Ws[(kq + 0) * 128 + o] = v.x;
            Ws[(kq + 1) * 128 + o] = v.y;
            Ws[(kq + 2) * 128 + o] = v.z;
            Ws[(kq + 3) * 128 + o] = v.w;
        }
        __syncthreads();

#pragma unroll
        for (int kk = 0; kk < 32; kk++) {
            float4 w = *(const float4*)(Ws + kk * 128 + col_tile * 4);  // 128b LDS, conflict-free
#pragma unroll
            for (int r = 0; r < 8; r++) {
                float a = As[(row_tile * 8 + r) * 32 + kk];             // warp-uniform broadcast
                acc[r][0] += a * w.x;
                acc[r][1] += a * w.y;
                acc[r][2] += a * w.z;
                acc[r][3] += a * w.w;
            }
        }
        __syncthreads();
    }

    // --- epilogue: scale by dis[row], add bias, write both buffers ---
    float4 bb = *(const float4*)(b + col_tile * 4);
#pragma unroll
    for (int r = 0; r < 8; r++) {
        int grow = block_row + row_tile * 8 + r;
        if (grow < n) {
            float s = dis[grow];
            float4 v;
            v.x = s * (acc[r][0] + bb.x);
            v.y = s * (acc[r][1] + bb.y);
            v.z = s * (acc[r][2] + bb.z);
            v.w = s * (acc[r][3] + bb.w);
            size_t off = (size_t)grow * D_FEAT + col_tile * 4;
            *(float4*)(out_h + off)   = v;
            *(float4*)(out_agg + off) = v;   // self-loop term pre-seeded
        }
    }
}

// ---------------------------------------------------------------------------
// Edge scatter: warp per edge. agg[col] += h[row]  (128 floats = 32 lanes x float4)
// ---------------------------------------------------------------------------
__global__ __launch_bounds__(256) void scatter_kernel(
    const int2* __restrict__ edges, const float* __restrict__ h,
    float* __restrict__ agg, int e)
{
    long long t = (long long)blockIdx.x * blockDim.x + threadIdx.x;
    int edge = (int)(t >> 5);
    int lane = (int)(t & 31);
    if (edge >= e) return;
    int2 rc = __ldg(edges + edge);              // warp-uniform -> 1 broadcast request
    float4 v = *(const float4*)(h + (size_t)rc.x * D_FEAT + lane * 4);
    float* p = agg + (size_t)rc.y * D_FEAT + lane * 4;
    asm volatile("red.global.add.v4.f32 [%0], {%1,%2,%3,%4};"
                 :: "l"(p), "f"(v.x), "f"(v.y), "f"(v.z), "f"(v.w) : "memory");
}

// ---------------------------------------------------------------------------
// Final epilogue: out[i] = relu(dis[i] * agg[i])
// ---------------------------------------------------------------------------
__global__ __launch_bounds__(256) void finalize_kernel(
    const float* __restrict__ agg, const float* __restrict__ dis,
    float* __restrict__ out, int n)
{
    int tid = blockIdx.x * blockDim.x + threadIdx.x;          // over n * 32 float4s
    int total = n * (D_FEAT / 4);
    if (tid >= total) return;
    int row = tid >> 5;                                       // 32 float4 per row
    float s = dis[row];
    float4 v = ((const float4*)agg)[tid];
    v.x = fmaxf(s * v.x, 0.f);
    v.y = fmaxf(s * v.y, 0.f);
    v.z = fmaxf(s * v.z, 0.f);
    v.w = fmaxf(s * v.w, 0.f);
    ((float4*)out)[tid] = v;
}

// ---------------------------------------------------------------------------
// Launch
// ---------------------------------------------------------------------------
extern "C" void kernel_launch(void* const* d_in, const int* in_sizes, int n_in,
                              void* d_out, int out_size)
{
    const float* x  = (const float*)d_in[0];
    const int*   ei = (const int*)d_in[1];      // JAX x64 disabled -> int32
    const float* W1 = (const float*)d_in[2];
    const float* b1 = (const float*)d_in[3];
    const float* W2 = (const float*)d_in[4];
    const float* b2 = (const float*)d_in[5];
    const float* W3 = (const float*)d_in[6];
    const float* b3 = (const float*)d_in[7];
    float* out = (float*)d_out;

    float *h, *agg, *deg, *dis;
    int2* edges;
    cudaGetSymbolAddress((void**)&h,     g_h);
    cudaGetSymbolAddress((void**)&agg,   g_agg);
    cudaGetSymbolAddress((void**)&deg,   g_deg);
    cudaGetSymbolAddress((void**)&dis,   g_dis);
    cudaGetSymbolAddress((void**)&edges, g_edges);

    const int n = N_NODES, e = E_EDGES;

    // degrees + dis = deg^-1/2, and pack edges to int2
    deg_init_kernel<<<(n + 255) / 256, 256>>>(deg, n);
    edge_pack_kernel<<<(e + 255) / 256, 256>>>(ei, edges, deg, e);
    deg_fin_kernel<<<(n + 255) / 256, 256>>>(deg, dis, n);

    const int gemm_blocks = (n + 63) / 64;
    const long long scatter_threads = (long long)e * 32;
    const int scatter_blocks = (int)((scatter_threads + 255) / 256);

    // Layer 1 (raw x input)
    gemm_kernel<false><<<gemm_blocks, 256>>>(x, W1, b1, dis, h, agg, n);
    scatter_kernel<<<scatter_blocks, 256>>>(edges, h, agg, e);

    // Layer 2 (fused relu(dis*agg) on load)
    gemm_kernel<true><<<gemm_blocks, 256>>>(agg, W2, b2, dis, h, agg, n);
    scatter_kernel<<<scatter_blocks, 256>>>(edges, h, agg, e);

    // Layer 3
    gemm_kernel<true><<<gemm_blocks, 256>>>(agg, W3, b3, dis, h, agg, n);
    scatter_kernel<<<scatter_blocks, 256>>>(edges, h, agg, e);

    // out = relu(dis * agg)
    finalize_kernel<<<(n * (D_FEAT / 4) + 255) / 256, 256>>>(agg, dis, out, n);
}

// round 4
// speedup vs baseline: 1.9787x; 1.9787x over previous
#include <cuda_runtime.h>
#include <cuda_bf16.h>
#include <cstdint>

// Problem constants (fixed by the reference)
#define N_NODES 100000
#define D_FEAT  128
#define E_EDGES 1600000

#define SCAN_CHUNK 256
#define NUM_CHUNKS ((N_NODES + SCAN_CHUNK - 1) / SCAN_CHUNK)   // 391

// Static device scratch (allocation-free rule: __device__ globals)
__device__ float g_h     [(size_t)N_NODES * D_FEAT];  // dis-scaled linear output
__device__ float g_agg   [(size_t)N_NODES * D_FEAT];  // aggregation buffer
__device__ float g_deg   [N_NODES];
__device__ float g_dis   [N_NODES];
__device__ int2  g_edges [E_EDGES];                   // packed (row, col)
__device__ int   g_colcnt[N_NODES];                   // in-degree histogram (by col)
__device__ int   g_colptr[N_NODES + 1];               // CSR offsets
__device__ int   g_cursor[N_NODES];                   // fill cursors
__device__ int   g_csrrow[E_EDGES];                   // CSR source (row) indices
__device__ int   g_partial[NUM_CHUNKS];               // scan partials

// ---------------------------------------------------------------------------
// Setup: degree init + edge packing + histograms
// ---------------------------------------------------------------------------
__global__ void init_kernel(float* __restrict__ deg, int* __restrict__ colcnt, int n) {
    int i = blockIdx.x * blockDim.x + threadIdx.x;
    if (i < n) { deg[i] = 1.0f; colcnt[i] = 0; }   // self-loop seeds deg with 1
}

__global__ void edge_pack_kernel(const int* __restrict__ ei,
                                 int2* __restrict__ edges,
                                 float* __restrict__ deg,
                                 int* __restrict__ colcnt, int e) {
    int i = blockIdx.x * blockDim.x + threadIdx.x;
    if (i >= e) return;
    int r = ei[i];
    int c = ei[E_EDGES + i];
    // defensive clamp (keeps CSR counts consistent; indices are valid in practice)
    if ((unsigned)r >= (unsigned)N_NODES) r = 0;
    if ((unsigned)c >= (unsigned)N_NODES) c = 0;
    edges[i] = make_int2(r, c);
    atomicAdd(&deg[r], 1.0f);        // row-side degree (matches reference)
    atomicAdd(&colcnt[c], 1);        // col-side histogram for CSR
}

__global__ void deg_fin_kernel(const float* __restrict__ deg, float* __restrict__ dis, int n) {
    int i = blockIdx.x * blockDim.x + threadIdx.x;
    if (i < n) dis[i] = rsqrtf(deg[i]);
}

// ---------------------------------------------------------------------------
// Two-level exclusive scan of colcnt -> colptr (+ cursor copy)
// ---------------------------------------------------------------------------
__global__ void scan_block_sums(const int* __restrict__ colcnt, int* __restrict__ partial, int n) {
    __shared__ int sh[SCAN_CHUNK];
    int b = blockIdx.x, t = threadIdx.x, i = b * SCAN_CHUNK + t;
    sh[t] = (i < n) ? colcnt[i] : 0;
    __syncthreads();
    for (int of = SCAN_CHUNK / 2; of > 0; of >>= 1) {
        if (t < of) sh[t] += sh[t + of];
        __syncthreads();
    }
    if (t == 0) partial[b] = sh[0];
}

__global__ void scan_partials_kernel(int* __restrict__ partial, int* __restrict__ colptr, int nb) {
    __shared__ int sh[512];
    int t = threadIdx.x;
    int v = (t < nb) ? partial[t] : 0;
    sh[t] = v;
    __syncthreads();
    for (int of = 1; of < 512; of <<= 1) {
        int x = (t >= of) ? sh[t - of] : 0;
        __syncthreads();
        sh[t] += x;
        __syncthreads();
    }
    if (t < nb) partial[t] = sh[t] - v;   // exclusive
    if (t == 0) colptr[N_NODES] = E_EDGES;
}

__global__ void scan_chunks_kernel(const int* __restrict__ colcnt,
                                   const int* __restrict__ partial,
                                   int* __restrict__ colptr,
                                   int* __restrict__ cursor, int n) {
    __shared__ int sh[SCAN_CHUNK];
    int b = blockIdx.x, t = threadIdx.x, i = b * SCAN_CHUNK + t;
    int v = (i < n) ? colcnt[i] : 0;
    sh[t] = v;
    __syncthreads();
    for (int of = 1; of < SCAN_CHUNK; of <<= 1) {
        int x = (t >= of) ? sh[t - of] : 0;
        __syncthreads();
        sh[t] += x;
        __syncthreads();
    }
    if (i < n) {
        int excl = sh[t] - v + partial[b];
        colptr[i] = excl;
        cursor[i] = excl;
    }
}

__global__ void csr_fill_kernel(const int2* __restrict__ edges,
                                int* __restrict__ cursor,
                                int* __restrict__ csrrow, int e) {
    int i = blockIdx.x * blockDim.x + threadIdx.x;
    if (i >= e) return;
    int2 rc = edges[i];
    int pos = atomicAdd(&cursor[rc.y], 1);
    csrrow[pos] = rc.x;
}

// ---------------------------------------------------------------------------
// GEMM: out_h[i] = dis[i] * (act(in[i]) @ W^T + b)
//   PRE==false: act(v) = v                  (layer 1, raw x input)
//   PRE==true : act(v) = relu(dis[i] * v)   (layers 2/3, fused prior epilogue)
// BM=128, BN=128, BK=16, 256 threads, 8x8 microtile, k-major smem tiles,
// all inner-loop smem accesses are conflict-free LDS.128.
// ---------------------------------------------------------------------------
template <bool PRE>
__global__ __launch_bounds__(256) void gemm_kernel(
    const float* __restrict__ in, const float* __restrict__ W,
    const float* __restrict__ b,  const float* __restrict__ dis,
    float* __restrict__ out_h, int n)
{
    __shared__ float As[16 * 128];   // [k][m]  (transposed)
    __shared__ float Ws[16 * 128];   // [k][o]  (transposed)

    const int tx = threadIdx.x;
    const int block_row = blockIdx.x * 128;
    const int mrow = tx >> 4;        // 0..15 -> rows mrow*8 .. +7
    const int ncol = tx & 15;        // cols ncol*4..+3 and 64+ncol*4..+3

    float acc[8][8];
#pragma unroll
    for (int r = 0; r < 8; r++)
#pragma unroll
        for (int c = 0; c < 8; c++) acc[r][c] = 0.0f;

    for (int k0 = 0; k0 < D_FEAT; k0 += 16) {
        // --- A tile: 128 rows x 16 k = 512 float4, 2 per thread, transposed store ---
#pragma unroll
        for (int it = 0; it < 2; it++) {
            int idx = it * 256 + tx;             // 0..511
            int r   = idx >> 2;                  // 4 float4 per row
            int c4  = (idx & 3) * 4;
            int grow = block_row + r;
            float4 v = make_float4(0.f, 0.f, 0.f, 0.f);
            if (grow < n) {
                v = *(const float4*)(in + (size_t)grow * D_FEAT + k0 + c4);
                if (PRE) {
                    float s = dis[grow];
                    v.x = fmaxf(v.x * s, 0.f);
                    v.y = fmaxf(v.y * s, 0.f);
                    v.z = fmaxf(v.z * s, 0.f);
                    v.w = fmaxf(v.w * s, 0.f);
                }
            }
            As[(c4 + 0) * 128 + r] = v.x;
            As[(c4 + 1) * 128 + r] = v.y;
            As[(c4 + 2) * 128 + r] = v.z;
            As[(c4 + 3) * 128 + r] = v.w;
        }
        // --- W tile: 128 o x 16 k = 512 float4, transposed store ---
#pragma unroll
        for (int it = 0; it < 2; it++) {
            int idx = it * 256 + tx;
            int o   = idx >> 2;
            int kq  = (idx & 3) * 4;
            float4 v = *(const float4*)(W + (size_t)o * D_FEAT + k0 + kq);
            Ws[(kq + 0) * 128 + o] = v.x;
            Ws[(kq + 1) * 128 + o] = v.y;
            Ws[(kq + 2) * 128 + o] = v.z;
            Ws[(kq + 3) * 128 + o] = v.w;
        }
        __syncthreads();

#pragma unroll
        for (int kk = 0; kk < 16; kk++) {
            float4 a0 = *(const float4*)(As + kk * 128 + mrow * 8);
            float4 a1 = *(const float4*)(As + kk * 128 + mrow * 8 + 4);
            float4 w0 = *(const float4*)(Ws + kk * 128 + ncol * 4);
            float4 w1 = *(const float4*)(Ws + kk * 128 + 64 + ncol * 4);
            float a[8] = {a0.x, a0.y, a0.z, a0.w, a1.x, a1.y, a1.z, a1.w};
            float w[8] = {w0.x, w0.y, w0.z, w0.w, w1.x, w1.y, w1.z, w1.w};
#pragma unroll
            for (int r = 0; r < 8; r++)
#pragma unroll
                for (int c = 0; c < 8; c++) acc[r][c] += a[r] * w[c];
        }
        __syncthreads();
    }

    // --- epilogue: scale by dis[row], add bias ---
    float4 b0 = *(const float4*)(b + ncol * 4);
    float4 b1 = *(const float4*)(b + 64 + ncol * 4);
#pragma unroll
    for (int r = 0; r < 8; r++) {
        int grow = block_row + mrow * 8 + r;
        if (grow < n) {
            float s = dis[grow];
            float4 v0, v1;
            v0.x = s * (acc[r][0] + b0.x);
            v0.y = s * (acc[r][1] + b0.y);
            v0.z = s * (acc[r][2] + b0.z);
            v0.w = s * (acc[r][3] + b0.w);
            v1.x = s * (acc[r][4] + b1.x);
            v1.y = s * (acc[r][5] + b1.y);
            v1.z = s * (acc[r][6] + b1.z);
            v1.w = s * (acc[r][7] + b1.w);
            size_t off = (size_t)grow * D_FEAT;
            *(float4*)(out_h + off + ncol * 4)      = v0;
            *(float4*)(out_h + off + 64 + ncol * 4) = v1;
        }
    }
}

// ---------------------------------------------------------------------------
// CSR aggregation: warp per destination node. Atomic-free.
//   acc = h[c] (self-loop) + sum_{r in in-neighbors(c)} h[r]
//   FINAL=0: agg[c] = acc          FINAL=1: out[c] = relu(dis[c]*acc)
// ---------------------------------------------------------------------------
__global__ __launch_bounds__(256) void agg_kernel(
    const int* __restrict__ colptr, const int* __restrict__ csrrow,
    const float* __restrict__ h, const float* __restrict__ dis,
    float* __restrict__ outp, int n, int final_relu)
{
    int w    = (blockIdx.x * blockDim.x + threadIdx.x) >> 5;
    int lane = threadIdx.x & 31;
    if (w >= n) return;

    size_t fo = (size_t)lane * 4;
    float4 acc = *(const float4*)(h + (size_t)w * D_FEAT + fo);   // self-loop term

    int beg = __ldg(colptr + w);
    int end = __ldg(colptr + w + 1);
    int i = beg;
    for (; i + 3 < end; i += 4) {
        int r0 = __ldg(csrrow + i);
        int r1 = __ldg(csrrow + i + 1);
        int r2 = __ldg(csrrow + i + 2);
        int r3 = __ldg(csrrow + i + 3);
        float4 v0 = *(const float4*)(h + (size_t)r0 * D_FEAT + fo);
        float4 v1 = *(const float4*)(h + (size_t)r1 * D_FEAT + fo);
        float4 v2 = *(const float4*)(h + (size_t)r2 * D_FEAT + fo);
        float4 v3 = *(const float4*)(h + (size_t)r3 * D_FEAT + fo);
        acc.x += v0.x + v1.x + v2.x + v3.x;
        acc.y += v0.y + v1.y + v2.y + v3.y;
        acc.z += v0.z + v1.z + v2.z + v3.z;
        acc.w += v0.w + v1.w + v2.w + v3.w;
    }
    for (; i < end; i++) {
        int r = __ldg(csrrow + i);
        float4 v = *(const float4*)(h + (size_t)r * D_FEAT + fo);
        acc.x += v.x; acc.y += v.y; acc.z += v.z; acc.w += v.w;
    }

    if (final_relu) {
        float s = dis[w];
        acc.x = fmaxf(s * acc.x, 0.f);
        acc.y = fmaxf(s * acc.y, 0.f);
        acc.z = fmaxf(s * acc.z, 0.f);
        acc.w = fmaxf(s * acc.w, 0.f);
    }
    *(float4*)(outp + (size_t)w * D_FEAT + fo) = acc;
}

// ---------------------------------------------------------------------------
// Launch
// ---------------------------------------------------------------------------
extern "C" void kernel_launch(void* const* d_in, const int* in_sizes, int n_in,
                              void* d_out, int out_size)
{
    const float* x  = (const float*)d_in[0];
    const int*   ei = (const int*)d_in[1];      // JAX x64 disabled -> int32
    const float* W1 = (const float*)d_in[2];
    const float* b1 = (const float*)d_in[3];
    const float* W2 = (const float*)d_in[4];
    const float* b2 = (const float*)d_in[5];
    const float* W3 = (const float*)d_in[6];
    const float* b3 = (const float*)d_in[7];
    float* out = (float*)d_out;

    float *h, *agg, *deg, *dis;
    int2* edges;
    int *colcnt, *colptr, *cursor, *csrrow, *partial;
    cudaGetSymbolAddress((void**)&h,       g_h);
    cudaGetSymbolAddress((void**)&agg,     g_agg);
    cudaGetSymbolAddress((void**)&deg,     g_deg);
    cudaGetSymbolAddress((void**)&dis,     g_dis);
    cudaGetSymbolAddress((void**)&edges,   g_edges);
    cudaGetSymbolAddress((void**)&colcnt,  g_colcnt);
    cudaGetSymbolAddress((void**)&colptr,  g_colptr);
    cudaGetSymbolAddress((void**)&cursor,  g_cursor);
    cudaGetSymbolAddress((void**)&csrrow,  g_csrrow);
    cudaGetSymbolAddress((void**)&partial, g_partial);

    const int n = N_NODES, e = E_EDGES;

    // Setup: degrees, normalization, CSR by destination
    init_kernel<<<(n + 255) / 256, 256>>>(deg, colcnt, n);
    edge_pack_kernel<<<(e + 255) / 256, 256>>>(ei, edges, deg, colcnt, e);
    deg_fin_kernel<<<(n + 255) / 256, 256>>>(deg, dis, n);
    scan_block_sums<<<NUM_CHUNKS, SCAN_CHUNK>>>(colcnt, partial, n);
    scan_partials_kernel<<<1, 512>>>(partial, colptr, NUM_CHUNKS);
    scan_chunks_kernel<<<NUM_CHUNKS, SCAN_CHUNK>>>(colcnt, partial, colptr, cursor, n);
    csr_fill_kernel<<<(e + 255) / 256, 256>>>(edges, cursor, csrrow, e);

    const int gemm_blocks = (n + 127) / 128;
    const int agg_blocks  = (int)(((long long)n * 32 + 255) / 256);

    // Layer 1
    gemm_kernel<false><<<gemm_blocks, 256>>>(x, W1, b1, dis, h, n);
    agg_kernel<<<agg_blocks, 256>>>(colptr, csrrow, h, dis, agg, n, 0);

    // Layer 2
    gemm_kernel<true><<<gemm_blocks, 256>>>(agg, W2, b2, dis, h, n);
    agg_kernel<<<agg_blocks, 256>>>(colptr, csrrow, h, dis, agg, n, 0);

    // Layer 3 (final relu fused into aggregation, writes d_out)
    gemm_kernel<true><<<gemm_blocks, 256>>>(agg, W3, b3, dis, h, n);
    agg_kernel<<<agg_blocks, 256>>>(colptr, csrrow, h, dis, out, n, 1);
}